// round 10
// baseline (speedup 1.0000x reference)
#include <cuda_runtime.h>
#include <math.h>

#define NN 128
#define PITCHD 130   // float2 pitch: conflict-free LDS.128 row reads
#define BATCH 512
#define NPAIRS 8128
#define NT 512
#define SEGJ 32
#define TSTEPS 10

typedef unsigned long long ull;

struct __align__(16) Smem {
  float2 DW[NN * PITCHD];   // (d,w) pairs, row-major, symmetric
  float4 Xs[NN];            // coordinates, .w = |x|^2
  float4 part[3 * NN];      // cross-group partials
  unsigned bits[NN * 4];    // adjacency bitmask
  float rs[NN];             // row sums of D^2 (built by atomics in A2)
  float u[NN];              // power-iteration vector
  float scal[8];
  int icnt[4];
};

__device__ __forceinline__ float softplus_f(float x) {
  return fmaxf(x, 0.0f) + __logf(1.0f + __expf(-fabsf(x)));
}
__device__ __forceinline__ ull pk2(float lo, float hi) {
  ull r; asm("mov.b64 %0, {%1, %2};" : "=l"(r) : "f"(lo), "f"(hi)); return r;
}
__device__ __forceinline__ void upk2(ull v, float& lo, float& hi) {
  asm("mov.b64 {%0, %1}, %2;" : "=f"(lo), "=f"(hi) : "l"(v));
}
__device__ __forceinline__ ull fma2(ull a, ull b, ull c) {
  ull d; asm("fma.rn.f32x2 %0, %1, %2, %3;" : "=l"(d) : "l"(a), "l"(b), "l"(c));
  return d;
}
__device__ __forceinline__ ull add2(ull a, ull b) {
  ull d; asm("add.rn.f32x2 %0, %1, %2;" : "=l"(d) : "l"(a), "l"(b));
  return d;
}

__global__ void __launch_bounds__(NT, 1)
ts_gcn_kernel(const float* __restrict__ edge_pred,
              const int*   __restrict__ adj,
              const float* __restrict__ d_init,
              const float* __restrict__ u_init,
              const float* __restrict__ x_noise,
              float*       __restrict__ out)
{
  extern __shared__ __align__(16) char smem_raw[];
  Smem* sm = reinterpret_cast<Smem*>(smem_raw);
  const int b    = blockIdx.x;
  const int tid  = threadIdx.x;
  const int lane = tid & 31;
  const int wid  = tid >> 5;
  const int i_d  = tid & (NN - 1);
  const int g    = tid >> 7;        // j-group 0..3
  const int j0   = g * SEGJ;
  const float d0 = __ldg(d_init);

  const float2* epb  = reinterpret_cast<const float2*>(edge_pred) + (size_t)b * NN * NN;
  const int*    adjb = adj + (size_t)b * NN * NN;

  if (tid == 0) sm->icnt[0] = 0;
  if (tid < NN) sm->rs[tid] = 0.0f;

  // ---- A1: stage raw edge_pred (coalesced LDG.64 -> STS) ---------------------
  #pragma unroll
  for (int v = 0; v < 32; ++v) {
    int idx = v * NT + tid;
    sm->DW[(idx >> 7) * PITCHD + (idx & (NN - 1))] = epb[idx];
  }
  // ---- A1b: adjacency bits via ballot ----------------------------------------
  #pragma unroll
  for (int v = 0; v < 32; ++v) {
    int word = v * 16 + wid;
    int i = word >> 2, q = word & 3;
    int a = adjb[i * NN + q * 32 + lane];
    unsigned m = __ballot_sync(0xffffffffu, a != 0);
    if (lane == 0) sm->bits[word] = m;
  }
  __syncthreads();

  // ---- A2: symmetrize + softplus + rs accumulation (upper triangle) ----------
  #pragma unroll
  for (int v = 0; v < 16; ++v) {
    int p = v * NT + tid;
    if (p < NPAIRS) {
      int r = p / 127, c = p - r * 127;
      int i, j;
      if (c >= r) { i = r; j = c + 1; }
      else        { i = 127 - r; j = 127 - c; }
      unsigned on = (sm->bits[(i << 2) + (j >> 5)] >> (j & 31)) & 1u;
      float2 e1 = sm->DW[i * PITCHD + j];
      float2 e2 = sm->DW[j * PITCHD + i];
      float2 dw = make_float2(0.0f, 0.0f);
      if (on) {
        dw.x = softplus_f(d0 + e1.x + e2.x);
        dw.y = softplus_f(d0 + e1.y + e2.y);
        float d2 = dw.x * dw.x;
        atomicAdd(&sm->rs[i], d2);      // row sums of D^2, both orientations
        atomicAdd(&sm->rs[j], d2);
      }
      sm->DW[i * PITCHD + j] = dw;
      sm->DW[j * PITCHD + i] = dw;
    }
  }
  if (tid < NN) sm->DW[tid * PITCHD + tid] = make_float2(0.0f, 0.0f);
  // sum(adj) via popc while atomics drain
  {
    int cbit = __popc(sm->bits[tid]);
    #pragma unroll
    for (int o = 16; o; o >>= 1) cbit += __shfl_xor_sync(0xffffffffu, cbit, o);
    if (lane == 0) atomicAdd(&sm->icnt[0], cbit);
  }
  __syncthreads();

  // ---- B: global scalars -------------------------------------------------------
  if (tid < 32) {
    float m = sm->rs[tid] + sm->rs[tid + 32] + sm->rs[tid + 64] + sm->rs[tid + 96];
    #pragma unroll
    for (int o = 16; o; o >>= 1) m += __shfl_xor_sync(0xffffffffu, m, o);
    if (tid == 0) {
      float Nmol = 1.0f + (float)(__popc(sm->bits[0]) + __popc(sm->bits[1]) +
                                  __popc(sm->bits[2]) + __popc(sm->bits[3]));
      float invN = 1.0f / Nmol;
      sm->scal[0] = invN;
      sm->scal[1] = m * invN * invN;
      float S = 128.0f + (float)sm->icnt[0];
      sm->scal[2] = 0.4f / S;          // 4*STEP_EPS / sum(mask)
    }
  }
  __syncthreads();

  // ---- B2: Gram matrix into registers ------------------------------------------
  float bg[SEGJ];
  {
    float invN = sm->scal[0], Moff = sm->scal[1];
    float rsi = sm->rs[i_d];
    unsigned wb = sm->bits[(i_d << 2) + (j0 >> 5)];
    const float4* drow = reinterpret_cast<const float4*>(sm->DW + i_d * PITCHD + j0);
    const float4* rsj  = reinterpret_cast<const float4*>(sm->rs + j0);
    #pragma unroll
    for (int t = 0; t < 8; ++t) {
      float4 rq = rsj[t];
      float4 q0 = drow[2 * t], q1 = drow[2 * t + 1];
      float dv[4] = {q0.x, q0.z, q1.x, q1.z};
      float rv[4] = {rq.x, rq.y, rq.z, rq.w};
      #pragma unroll
      for (int m = 0; m < 4; ++m) {
        int jj = 4 * t + m;
        int j = j0 + jj;
        bool on = (((wb >> jj) & 1u) != 0u) || (j == i_d);
        float val = -0.5f * (fmaf(dv[m], dv[m], Moff) - (rsi + rv[m]) * invN);
        bg[jj] = on ? val : 0.0f;
      }
    }
  }

  // ---- C: rank-3 power iteration, BG in regs, 4-way ILP -------------------------
  for (int k = 0; k < 3; ++k) {
    __syncthreads();
    if (tid < NN) sm->u[tid] = u_init[((size_t)b * NN + tid) * 3 + k];
    __syncthreads();
    for (int it = 0; it < 10; ++it) {
      float4 uv = reinterpret_cast<const float4*>(sm->u)[lane];
      float s = fmaf(uv.x, uv.x, fmaf(uv.y, uv.y, fmaf(uv.z, uv.z, uv.w * uv.w)));
      #pragma unroll
      for (int o = 16; o; o >>= 1) s += __shfl_xor_sync(0xffffffffu, s, o);
      float invn = rsqrtf(fmaxf(s, 1e-6f));  // == 1/max(sqrt(s), 0.001)
      float a0 = 0.0f, a1 = 0.0f, a2 = 0.0f, a3 = 0.0f;
      const float4* useg = reinterpret_cast<const float4*>(sm->u + j0);
      #pragma unroll
      for (int t = 0; t < 8; ++t) {
        float4 uq = useg[t];
        a0 = fmaf(bg[4 * t + 0], uq.x, a0);
        a1 = fmaf(bg[4 * t + 1], uq.y, a1);
        a2 = fmaf(bg[4 * t + 2], uq.z, a2);
        a3 = fmaf(bg[4 * t + 3], uq.w, a3);
      }
      float acc = (a0 + a1) + (a2 + a3);
      if (g) sm->part[(g - 1) * NN + i_d].x = acc;
      __syncthreads();
      if (g == 0) {
        acc += sm->part[i_d].x + sm->part[NN + i_d].x + sm->part[2 * NN + i_d].x;
        sm->u[i_d] = acc * invn;
      }
      __syncthreads();
    }
    float4 uv = reinterpret_cast<const float4*>(sm->u)[lane];
    float s = fmaf(uv.x, uv.x, fmaf(uv.y, uv.y, fmaf(uv.z, uv.z, uv.w * uv.w)));
    #pragma unroll
    for (int o = 16; o; o >>= 1) s += __shfl_xor_sync(0xffffffffu, s, o);
    float sc4 = rsqrtf(sqrtf(s + 0.01f));    // (eig_sq + 0.01)^-0.25
    __syncthreads();
    if (tid < NN) {
      float uk = sm->u[tid] * sc4;
      sm->u[tid] = uk;
      reinterpret_cast<float*>(&sm->Xs[tid])[k] =
          uk + x_noise[((size_t)b * NN + tid) * 3 + k];
    }
    __syncthreads();
    if (k < 2) {
      float ui = sm->u[i_d];
      const float4* useg = reinterpret_cast<const float4*>(sm->u + j0);
      #pragma unroll
      for (int t = 0; t < 8; ++t) {
        float4 uq = useg[t];
        bg[4 * t + 0] = fmaf(-ui, uq.x, bg[4 * t + 0]);
        bg[4 * t + 1] = fmaf(-ui, uq.y, bg[4 * t + 1]);
        bg[4 * t + 2] = fmaf(-ui, uq.z, bg[4 * t + 2]);
        bg[4 * t + 3] = fmaf(-ui, uq.w, bg[4 * t + 3]);
      }
    }
  }
  // finalize Xs.w = |x|^2
  if (tid < NN) {
    float4 x = sm->Xs[tid];
    x.w = fmaf(x.x, x.x, fmaf(x.y, x.y, x.z * x.z));
    sm->Xs[tid] = x;
  }

  // ---- preload packed (w*d) and (-w) for all 10 steps ---------------------------
  ull wd2[SEGJ / 2], wn2[SEGJ / 2];
  {
    const float4* drow = reinterpret_cast<const float4*>(sm->DW + i_d * PITCHD + j0);
    #pragma unroll
    for (int t = 0; t < 16; ++t) {
      float4 q = drow[t];                    // (d0,w0,d1,w1)
      wd2[t] = pk2(q.x * q.y, q.z * q.w);
      wn2[t] = pk2(-q.y, -q.w);
    }
  }
  const float cc = sm->scal[2];
  __syncthreads();

  // ---- D: 10 gradient-descent steps, packed f32x2, AoS X loads ------------------
  for (int ts = 0; ts < TSTEPS; ++ts) {
    float alpha = 0.1f + 4.9f * ((float)(TSTEPS - ts) * 0.1f);
    float4 xi = sm->Xs[i_d];
    ull m2x2 = pk2(-2.0f * xi.x, -2.0f * xi.x);
    ull m2y2 = pk2(-2.0f * xi.y, -2.0f * xi.y);
    ull m2z2 = pk2(-2.0f * xi.z, -2.0f * xi.z);
    float cbase = xi.w + 0.01f;
    ull cbase2 = pk2(cbase, cbase);
    ull cs2 = 0ull, ax2 = 0ull, ay2 = 0ull, az2 = 0ull;
    const float4* xrow = sm->Xs + j0;
    #pragma unroll
    for (int t = 0; t < SEGJ / 2; ++t) {
      float4 xa = xrow[2 * t];               // LDS.128 broadcast
      float4 xb = xrow[2 * t + 1];           // LDS.128 broadcast
      ull xjx = pk2(xa.x, xb.x);
      ull xjy = pk2(xa.y, xb.y);
      ull xjz = pk2(xa.z, xb.z);
      ull xjw = pk2(xa.w, xb.w);
      ull s2p = fma2(xjx, m2x2, xjw);
      s2p = fma2(xjy, m2y2, s2p);
      s2p = fma2(xjz, m2z2, s2p);
      s2p = add2(s2p, cbase2);               // |xi-xj|^2 + 0.01 (two j's)
      float s0, s1;
      upk2(s2p, s0, s1);
      ull r2 = pk2(rsqrtf(s0), rsqrtf(s1));
      ull coef2 = fma2(wd2[t], r2, wn2[t]);  // w*(d/Dx - 1), packed
      cs2 = add2(cs2, coef2);
      ax2 = fma2(coef2, xjx, ax2);
      ay2 = fma2(coef2, xjy, ay2);
      az2 = fma2(coef2, xjz, az2);
    }
    float csl, csh, axl, axh, ayl, ayh, azl, azh;
    upk2(cs2, csl, csh); upk2(ax2, axl, axh);
    upk2(ay2, ayl, ayh); upk2(az2, azl, azh);
    float cs = csl + csh, ax = axl + axh, ay = ayl + ayh, az = azl + azh;
    if (g) sm->part[(g - 1) * NN + i_d] = make_float4(ax, ay, az, cs);
    __syncthreads();
    if (g == 0) {
      float4 p1 = sm->part[i_d], p2 = sm->part[NN + i_d], p3 = sm->part[2 * NN + i_d];
      float AX = ax + p1.x + p2.x + p3.x;
      float AY = ay + p1.y + p2.y + p3.y;
      float AZ = az + p1.z + p2.z + p3.z;
      float CS = cs + p1.w + p2.w + p3.w;
      float gx = fmaf(CS, xi.x, -AX) * cc;
      float gy = fmaf(CS, xi.y, -AY) * cc;
      float gz = fmaf(CS, xi.z, -AZ) * cc;
      float s2 = fmaf(gx, gx, fmaf(gy, gy, fmaf(gz, gz, 0.001f)));
      float inv_sp = rsqrtf(s2);
      float sp = s2 * inv_sp;
      float e = __expf(2.0f * (sp / alpha));
      float th = 1.0f - __fdividef(2.0f, e + 1.0f);
      float sc = alpha * th * inv_sp;
      xi.x = fmaf(gx, sc, xi.x);
      xi.y = fmaf(gy, sc, xi.y);
      xi.z = fmaf(gz, sc, xi.z);
      xi.w = fmaf(xi.x, xi.x, fmaf(xi.y, xi.y, xi.z * xi.z));
      sm->Xs[i_d] = xi;
    }
    __syncthreads();
  }

  // ---- E: output = adj * distances(X); sqrt via s*rsqrt(s) ----------------------
  float* outb = out + (size_t)b * NN * NN;
  #pragma unroll
  for (int v = 0; v < 8; ++v) {
    int f = v * NT + tid;
    int i = f >> 5;
    int jb = (f & 31) * 4;
    float4 xi = sm->Xs[i];
    unsigned wb = sm->bits[(i << 2) + (jb >> 5)];
    float4 r;
    #pragma unroll
    for (int m = 0; m < 4; ++m) {
      int j = jb + m;
      float4 xj = sm->Xs[j];
      float dx = xi.x - xj.x, dy = xi.y - xj.y, dz = xi.z - xj.z;
      float s = fmaf(dx, dx, fmaf(dy, dy, fmaf(dz, dz, 0.01f)));
      float val = ((wb >> (j & 31)) & 1u) ? s * rsqrtf(s) : 0.0f;
      reinterpret_cast<float*>(&r)[m] = val;
    }
    reinterpret_cast<float4*>(outb)[f] = r;
  }
}

extern "C" void kernel_launch(void* const* d_in, const int* in_sizes, int n_in,
                              void* d_out, int out_size) {
  const float* edge_pred = (const float*)d_in[0];
  const int*   adj       = (const int*)  d_in[1];
  const float* d_init    = (const float*)d_in[2];
  const float* u_init    = (const float*)d_in[3];
  const float* x_noise   = (const float*)d_in[4];
  float* out = (float*)d_out;

  size_t smem = sizeof(Smem);
  cudaFuncSetAttribute(ts_gcn_kernel,
                       cudaFuncAttributeMaxDynamicSharedMemorySize, (int)smem);
  ts_gcn_kernel<<<BATCH, NT, smem>>>(edge_pred, adj, d_init, u_init,
                                     x_noise, out);
}

// round 11
// speedup vs baseline: 1.2662x; 1.2662x over previous
#include <cuda_runtime.h>
#include <cuda_fp16.h>
#include <math.h>

#define NN 128
#define BATCH 512
#define NB 2          // batches per CTA
#define NPAIRS 8128
#define NT 512
#define SEGJ 32
#define TSTEPS 10

struct __align__(16) Smem {
  float2 tri[NB][NPAIRS];    // (d,w) per unordered pair, per batch (127 KB)
  float4 Xs[NB][NN];         // coordinates, .w = |x|^2
  float4 part[NB][3 * NN];   // cross-group partials
  unsigned bits[NB][NN * 4]; // adjacency bitmasks
  float rs[NB][NN];
  float u[NB][NN];
  float scal[NB][8];
  int icnt[NB][4];
};                           // ~149 KB -> 1 CTA/SM

__device__ __forceinline__ int tidx(int i, int j) {
  int a = min(i, j), b = max(i, j);
  return ((a * (255 - a)) >> 1) + b - a - 1;
}
__device__ __forceinline__ float softplus_f(float x) {
  return fmaxf(x, 0.0f) + __logf(1.0f + __expf(-fabsf(x)));
}

__global__ void __launch_bounds__(NT, 1)
ts_gcn_kernel(const float* __restrict__ edge_pred,
              const int*   __restrict__ adj,
              const float* __restrict__ d_init,
              const float* __restrict__ u_init,
              const float* __restrict__ x_noise,
              float*       __restrict__ out)
{
  extern __shared__ __align__(16) char smem_raw[];
  Smem* sm = reinterpret_cast<Smem*>(smem_raw);
  const int b0   = blockIdx.x * NB;
  const int tid  = threadIdx.x;
  const int lane = tid & 31;
  const int wid  = tid >> 5;
  const int i_d  = tid & (NN - 1);
  const int g    = tid >> 7;        // j-group 0..3
  const int j0   = g * SEGJ;
  const float d0 = __ldg(d_init);

  if (tid < NB) sm->icnt[tid][0] = 0;

  // ---- A1b: adjacency bits via ballot, both batches ---------------------------
  #pragma unroll
  for (int bb = 0; bb < NB; ++bb) {
    const int* adjb = adj + (size_t)(b0 + bb) * NN * NN;
    #pragma unroll
    for (int v = 0; v < 32; ++v) {
      int word = v * 16 + wid;
      int i = word >> 2, q = word & 3;
      int a = adjb[i * NN + q * 32 + lane];
      unsigned m = __ballot_sync(0xffffffffu, a != 0);
      if (lane == 0) sm->bits[bb][word] = m;
    }
  }
  __syncthreads();

  // ---- A2: symmetrize + softplus into triangle, both batches ------------------
  #pragma unroll
  for (int v = 0; v < 16; ++v) {
    int p = v * NT + tid;
    if (p < NPAIRS) {
      int r = p / 127, c = p - r * 127;
      int i, j;
      if (c >= r) { i = r; j = c + 1; }
      else        { i = 127 - r; j = 127 - c; }
      int idx = tidx(i, j);
      #pragma unroll
      for (int bb = 0; bb < NB; ++bb) {
        const float2* epb = reinterpret_cast<const float2*>(edge_pred)
                            + (size_t)(b0 + bb) * NN * NN;
        unsigned on = (sm->bits[bb][(i << 2) + (j >> 5)] >> (j & 31)) & 1u;
        float2 dw = make_float2(0.0f, 0.0f);
        if (on) {
          float2 e1 = epb[i * NN + j];
          float2 e2 = epb[j * NN + i];
          dw.x = softplus_f(d0 + e1.x + e2.x);
          dw.y = softplus_f(d0 + e1.y + e2.y);
        }
        sm->tri[bb][idx] = dw;
      }
    }
  }
  // sum(adj) popc while tri stores drain
  {
    int c0 = __popc(sm->bits[0][tid]);
    int c1 = __popc(sm->bits[1][tid]);
    #pragma unroll
    for (int o = 16; o; o >>= 1) {
      c0 += __shfl_xor_sync(0xffffffffu, c0, o);
      c1 += __shfl_xor_sync(0xffffffffu, c1, o);
    }
    if (lane == 0) {
      atomicAdd(&sm->icnt[0][0], c0);
      atomicAdd(&sm->icnt[1][0], c1);
    }
  }
  __syncthreads();

  // ---- B: row sums of D^2, both batches ---------------------------------------
  {
    float rp0 = 0.0f, rp1 = 0.0f;
    #pragma unroll 8
    for (int jj = 0; jj < SEGJ; ++jj) {
      int j = j0 + jj;
      if (j != i_d) {
        int idx = tidx(i_d, j);
        float da = sm->tri[0][idx].x;
        float db = sm->tri[1][idx].x;
        rp0 = fmaf(da, da, rp0);
        rp1 = fmaf(db, db, rp1);
      }
    }
    if (g) {
      sm->part[0][(g - 1) * NN + i_d].x = rp0;
      sm->part[1][(g - 1) * NN + i_d].x = rp1;
    }
    __syncthreads();
    if (g == 0) {
      rp0 += sm->part[0][i_d].x + sm->part[0][NN + i_d].x + sm->part[0][2 * NN + i_d].x;
      rp1 += sm->part[1][i_d].x + sm->part[1][NN + i_d].x + sm->part[1][2 * NN + i_d].x;
      sm->rs[0][i_d] = rp0;
      sm->rs[1][i_d] = rp1;
    }
  }
  __syncthreads();
  // ---- B scalars: warp 0 -> batch 0, warp 1 -> batch 1 ------------------------
  if (wid < NB) {
    int bb = wid;
    float m = sm->rs[bb][lane] + sm->rs[bb][lane + 32] +
              sm->rs[bb][lane + 64] + sm->rs[bb][lane + 96];
    #pragma unroll
    for (int o = 16; o; o >>= 1) m += __shfl_xor_sync(0xffffffffu, m, o);
    if (lane == 0) {
      float Nmol = 1.0f + (float)(__popc(sm->bits[bb][0]) + __popc(sm->bits[bb][1]) +
                                  __popc(sm->bits[bb][2]) + __popc(sm->bits[bb][3]));
      float invN = 1.0f / Nmol;
      sm->scal[bb][0] = invN;
      sm->scal[bb][1] = m * invN * invN;
      float S = 128.0f + (float)sm->icnt[bb][0];
      sm->scal[bb][2] = 0.4f / S;      // 4*STEP_EPS / sum(mask)
    }
  }
  __syncthreads();

  // ---- B2: Gram matrices into registers, both batches -------------------------
  float bg0[SEGJ], bg1[SEGJ];
  {
    float invN0 = sm->scal[0][0], Moff0 = sm->scal[0][1], rsi0 = sm->rs[0][i_d];
    float invN1 = sm->scal[1][0], Moff1 = sm->scal[1][1], rsi1 = sm->rs[1][i_d];
    unsigned wb0 = sm->bits[0][(i_d << 2) + (j0 >> 5)];
    unsigned wb1 = sm->bits[1][(i_d << 2) + (j0 >> 5)];
    #pragma unroll 8
    for (int jj = 0; jj < SEGJ; ++jj) {
      int j = j0 + jj;
      bool diag = (j == i_d);
      int idx = diag ? 0 : tidx(i_d, j);
      float da = diag ? 0.0f : sm->tri[0][idx].x;
      float db = diag ? 0.0f : sm->tri[1][idx].x;
      bool on0 = (((wb0 >> jj) & 1u) != 0u) || diag;
      bool on1 = (((wb1 >> jj) & 1u) != 0u) || diag;
      float v0 = -0.5f * (fmaf(da, da, Moff0) - (rsi0 + sm->rs[0][j]) * invN0);
      float v1 = -0.5f * (fmaf(db, db, Moff1) - (rsi1 + sm->rs[1][j]) * invN1);
      bg0[jj] = on0 ? v0 : 0.0f;
      bg1[jj] = on1 ? v1 : 0.0f;
    }
  }

  // ---- C: rank-3 power iteration, both batches --------------------------------
  for (int k = 0; k < 3; ++k) {
    __syncthreads();
    if (tid < NN) {
      sm->u[0][tid] = u_init[((size_t)b0 * NN + tid) * 3 + k];
      sm->u[1][tid] = u_init[((size_t)(b0 + 1) * NN + tid) * 3 + k];
    }
    __syncthreads();
    for (int it = 0; it < 10; ++it) {
      float4 uv0 = reinterpret_cast<const float4*>(sm->u[0])[lane];
      float4 uv1 = reinterpret_cast<const float4*>(sm->u[1])[lane];
      float s0 = fmaf(uv0.x, uv0.x, fmaf(uv0.y, uv0.y, fmaf(uv0.z, uv0.z, uv0.w * uv0.w)));
      float s1 = fmaf(uv1.x, uv1.x, fmaf(uv1.y, uv1.y, fmaf(uv1.z, uv1.z, uv1.w * uv1.w)));
      #pragma unroll
      for (int o = 16; o; o >>= 1) {
        s0 += __shfl_xor_sync(0xffffffffu, s0, o);
        s1 += __shfl_xor_sync(0xffffffffu, s1, o);
      }
      float invn0 = rsqrtf(fmaxf(s0, 1e-6f));
      float invn1 = rsqrtf(fmaxf(s1, 1e-6f));
      float a0 = 0.f, a1 = 0.f, b0a = 0.f, b1a = 0.f;
      const float4* us0 = reinterpret_cast<const float4*>(sm->u[0] + j0);
      const float4* us1 = reinterpret_cast<const float4*>(sm->u[1] + j0);
      #pragma unroll
      for (int t = 0; t < 8; ++t) {
        float4 uq0 = us0[t], uq1 = us1[t];
        a0 = fmaf(bg0[4 * t + 0], uq0.x, a0);
        a1 = fmaf(bg0[4 * t + 1], uq0.y, a1);
        a0 = fmaf(bg0[4 * t + 2], uq0.z, a0);
        a1 = fmaf(bg0[4 * t + 3], uq0.w, a1);
        b0a = fmaf(bg1[4 * t + 0], uq1.x, b0a);
        b1a = fmaf(bg1[4 * t + 1], uq1.y, b1a);
        b0a = fmaf(bg1[4 * t + 2], uq1.z, b0a);
        b1a = fmaf(bg1[4 * t + 3], uq1.w, b1a);
      }
      float acc0 = a0 + a1, acc1 = b0a + b1a;
      if (g) {
        sm->part[0][(g - 1) * NN + i_d].x = acc0;
        sm->part[1][(g - 1) * NN + i_d].x = acc1;
      }
      __syncthreads();
      if (g == 0) {
        acc0 += sm->part[0][i_d].x + sm->part[0][NN + i_d].x + sm->part[0][2 * NN + i_d].x;
        acc1 += sm->part[1][i_d].x + sm->part[1][NN + i_d].x + sm->part[1][2 * NN + i_d].x;
        sm->u[0][i_d] = acc0 * invn0;
        sm->u[1][i_d] = acc1 * invn1;
      }
      __syncthreads();
    }
    float4 uv0 = reinterpret_cast<const float4*>(sm->u[0])[lane];
    float4 uv1 = reinterpret_cast<const float4*>(sm->u[1])[lane];
    float s0 = fmaf(uv0.x, uv0.x, fmaf(uv0.y, uv0.y, fmaf(uv0.z, uv0.z, uv0.w * uv0.w)));
    float s1 = fmaf(uv1.x, uv1.x, fmaf(uv1.y, uv1.y, fmaf(uv1.z, uv1.z, uv1.w * uv1.w)));
    #pragma unroll
    for (int o = 16; o; o >>= 1) {
      s0 += __shfl_xor_sync(0xffffffffu, s0, o);
      s1 += __shfl_xor_sync(0xffffffffu, s1, o);
    }
    float sc40 = rsqrtf(sqrtf(s0 + 0.01f));
    float sc41 = rsqrtf(sqrtf(s1 + 0.01f));
    __syncthreads();
    if (tid < NN) {
      float uk0 = sm->u[0][tid] * sc40;
      float uk1 = sm->u[1][tid] * sc41;
      sm->u[0][tid] = uk0;
      sm->u[1][tid] = uk1;
      reinterpret_cast<float*>(&sm->Xs[0][tid])[k] =
          uk0 + x_noise[((size_t)b0 * NN + tid) * 3 + k];
      reinterpret_cast<float*>(&sm->Xs[1][tid])[k] =
          uk1 + x_noise[((size_t)(b0 + 1) * NN + tid) * 3 + k];
    }
    __syncthreads();
    if (k < 2) {
      float ui0 = sm->u[0][i_d], ui1 = sm->u[1][i_d];
      const float4* us0 = reinterpret_cast<const float4*>(sm->u[0] + j0);
      const float4* us1 = reinterpret_cast<const float4*>(sm->u[1] + j0);
      #pragma unroll
      for (int t = 0; t < 8; ++t) {
        float4 uq0 = us0[t], uq1 = us1[t];
        bg0[4 * t + 0] = fmaf(-ui0, uq0.x, bg0[4 * t + 0]);
        bg0[4 * t + 1] = fmaf(-ui0, uq0.y, bg0[4 * t + 1]);
        bg0[4 * t + 2] = fmaf(-ui0, uq0.z, bg0[4 * t + 2]);
        bg0[4 * t + 3] = fmaf(-ui0, uq0.w, bg0[4 * t + 3]);
        bg1[4 * t + 0] = fmaf(-ui1, uq1.x, bg1[4 * t + 0]);
        bg1[4 * t + 1] = fmaf(-ui1, uq1.y, bg1[4 * t + 1]);
        bg1[4 * t + 2] = fmaf(-ui1, uq1.z, bg1[4 * t + 2]);
        bg1[4 * t + 3] = fmaf(-ui1, uq1.w, bg1[4 * t + 3]);
      }
    }
  }
  // finalize Xs.w = |x|^2, both batches
  if (tid < NN) {
    #pragma unroll
    for (int bb = 0; bb < NB; ++bb) {
      float4 x = sm->Xs[bb][tid];
      x.w = fmaf(x.x, x.x, fmaf(x.y, x.y, x.z * x.z));
      sm->Xs[bb][tid] = x;
    }
  }

  // ---- preload (w*d, w) as half2 per j, both batches (bg dead) ----------------
  __half2 dwh0[SEGJ], dwh1[SEGJ];
  #pragma unroll 8
  for (int jj = 0; jj < SEGJ; ++jj) {
    int j = j0 + jj;
    bool diag = (j == i_d);
    int idx = diag ? 0 : tidx(i_d, j);
    float2 A = diag ? make_float2(0.f, 0.f) : sm->tri[0][idx];
    float2 B = diag ? make_float2(0.f, 0.f) : sm->tri[1][idx];
    dwh0[jj] = __floats2half2_rn(A.x * A.y, A.y);   // (w*d, w)
    dwh1[jj] = __floats2half2_rn(B.x * B.y, B.y);
  }
  const float cc0 = sm->scal[0][2];
  const float cc1 = sm->scal[1][2];
  __syncthreads();

  // ---- D: 10 gradient-descent steps, both batches -----------------------------
  for (int ts = 0; ts < TSTEPS; ++ts) {
    float alpha = 0.1f + 4.9f * ((float)(TSTEPS - ts) * 0.1f);
    float4 xi0 = sm->Xs[0][i_d], xi1 = sm->Xs[1][i_d];
    float m2x0 = -2.f * xi0.x, m2y0 = -2.f * xi0.y, m2z0 = -2.f * xi0.z;
    float m2x1 = -2.f * xi1.x, m2y1 = -2.f * xi1.y, m2z1 = -2.f * xi1.z;
    float cb0 = xi0.w + 0.01f, cb1 = xi1.w + 0.01f;
    float cs0 = 0.f, ax0 = 0.f, ay0 = 0.f, az0 = 0.f;
    float cs1 = 0.f, ax1 = 0.f, ay1 = 0.f, az1 = 0.f;
    const float4* xr0 = sm->Xs[0] + j0;
    const float4* xr1 = sm->Xs[1] + j0;
    #pragma unroll
    for (int jj = 0; jj < SEGJ; ++jj) {
      float4 xa = xr0[jj];                  // LDS.128 broadcast
      float4 xb = xr1[jj];
      float t0 = fmaf(xa.x, m2x0, xa.w);
      float t1 = fmaf(xb.x, m2x1, xb.w);
      t0 = fmaf(xa.y, m2y0, t0);
      t1 = fmaf(xb.y, m2y1, t1);
      t0 = fmaf(xa.z, m2z0, t0);
      t1 = fmaf(xb.z, m2z1, t1);
      float rinv0 = rsqrtf(t0 + cb0);
      float rinv1 = rsqrtf(t1 + cb1);
      float2 w0 = __half22float2(dwh0[jj]);
      float2 w1 = __half22float2(dwh1[jj]);
      float coef0 = fmaf(w0.x, rinv0, -w0.y);   // w*(d/Dx - 1)
      float coef1 = fmaf(w1.x, rinv1, -w1.y);
      cs0 += coef0;                 cs1 += coef1;
      ax0 = fmaf(coef0, xa.x, ax0); ax1 = fmaf(coef1, xb.x, ax1);
      ay0 = fmaf(coef0, xa.y, ay0); ay1 = fmaf(coef1, xb.y, ay1);
      az0 = fmaf(coef0, xa.z, az0); az1 = fmaf(coef1, xb.z, az1);
    }
    if (g) {
      sm->part[0][(g - 1) * NN + i_d] = make_float4(ax0, ay0, az0, cs0);
      sm->part[1][(g - 1) * NN + i_d] = make_float4(ax1, ay1, az1, cs1);
    }
    __syncthreads();
    if (g == 0) {
      #pragma unroll
      for (int r = 0; r < 3; ++r) {
        float4 p0 = sm->part[0][r * NN + i_d];
        float4 p1 = sm->part[1][r * NN + i_d];
        ax0 += p0.x; ay0 += p0.y; az0 += p0.z; cs0 += p0.w;
        ax1 += p1.x; ay1 += p1.y; az1 += p1.z; cs1 += p1.w;
      }
      float gx0 = fmaf(cs0, xi0.x, -ax0) * cc0;
      float gy0 = fmaf(cs0, xi0.y, -ay0) * cc0;
      float gz0 = fmaf(cs0, xi0.z, -az0) * cc0;
      float gx1 = fmaf(cs1, xi1.x, -ax1) * cc1;
      float gy1 = fmaf(cs1, xi1.y, -ay1) * cc1;
      float gz1 = fmaf(cs1, xi1.z, -az1) * cc1;
      float s20 = fmaf(gx0, gx0, fmaf(gy0, gy0, fmaf(gz0, gz0, 0.001f)));
      float s21 = fmaf(gx1, gx1, fmaf(gy1, gy1, fmaf(gz1, gz1, 0.001f)));
      float isp0 = rsqrtf(s20), isp1 = rsqrtf(s21);
      float sp0 = s20 * isp0,   sp1 = s21 * isp1;
      float e0 = __expf(2.0f * (sp0 / alpha));
      float e1 = __expf(2.0f * (sp1 / alpha));
      float th0 = 1.0f - __fdividef(2.0f, e0 + 1.0f);
      float th1 = 1.0f - __fdividef(2.0f, e1 + 1.0f);
      float sc0 = alpha * th0 * isp0;
      float sc1 = alpha * th1 * isp1;
      xi0.x = fmaf(gx0, sc0, xi0.x); xi1.x = fmaf(gx1, sc1, xi1.x);
      xi0.y = fmaf(gy0, sc0, xi0.y); xi1.y = fmaf(gy1, sc1, xi1.y);
      xi0.z = fmaf(gz0, sc0, xi0.z); xi1.z = fmaf(gz1, sc1, xi1.z);
      xi0.w = fmaf(xi0.x, xi0.x, fmaf(xi0.y, xi0.y, xi0.z * xi0.z));
      xi1.w = fmaf(xi1.x, xi1.x, fmaf(xi1.y, xi1.y, xi1.z * xi1.z));
      sm->Xs[0][i_d] = xi0;
      sm->Xs[1][i_d] = xi1;
    }
    __syncthreads();
  }

  // ---- E: output = adj * distances(X), both batches ---------------------------
  #pragma unroll
  for (int bb = 0; bb < NB; ++bb) {
    float* outb = out + (size_t)(b0 + bb) * NN * NN;
    #pragma unroll
    for (int v = 0; v < 8; ++v) {
      int f = v * NT + tid;
      int i = f >> 5;
      int jb = (f & 31) * 4;
      float4 xi = sm->Xs[bb][i];
      unsigned wb = sm->bits[bb][(i << 2) + (jb >> 5)];
      float4 r;
      #pragma unroll
      for (int m = 0; m < 4; ++m) {
        int j = jb + m;
        float4 xj = sm->Xs[bb][j];
        float dx = xi.x - xj.x, dy = xi.y - xj.y, dz = xi.z - xj.z;
        float s = fmaf(dx, dx, fmaf(dy, dy, fmaf(dz, dz, 0.01f)));
        float val = ((wb >> (j & 31)) & 1u) ? s * rsqrtf(s) : 0.0f;
        reinterpret_cast<float*>(&r)[m] = val;
      }
      reinterpret_cast<float4*>(outb)[f] = r;
    }
  }
}

extern "C" void kernel_launch(void* const* d_in, const int* in_sizes, int n_in,
                              void* d_out, int out_size) {
  const float* edge_pred = (const float*)d_in[0];
  const int*   adj       = (const int*)  d_in[1];
  const float* d_init    = (const float*)d_in[2];
  const float* u_init    = (const float*)d_in[3];
  const float* x_noise   = (const float*)d_in[4];
  float* out = (float*)d_out;

  size_t smem = sizeof(Smem);
  cudaFuncSetAttribute(ts_gcn_kernel,
                       cudaFuncAttributeMaxDynamicSharedMemorySize, (int)smem);
  ts_gcn_kernel<<<BATCH / NB, NT, smem>>>(edge_pred, adj, d_init, u_init,
                                          x_noise, out);
}

// round 12
// speedup vs baseline: 1.6694x; 1.3185x over previous
#include <cuda_runtime.h>
#include <math.h>

#define NN 128
#define PITCHD 130   // float2 pitch: conflict-free LDS.128 row reads
#define BATCH 512
#define NPAIRS 8128
#define NT 512
#define SEGJ 32
#define TSTEPS 10

typedef unsigned long long ull;

struct __align__(16) Smem {
  float2 DW[NN * PITCHD];   // (d,w) pairs, row-major, symmetric
  float4 Xs[NN];            // coordinates, .w = |x|^2
  float4 part[3 * NN];      // cross-group partials
  unsigned bits[NN * 4];    // adjacency bitmask
  float rs[NN];             // row sums of D^2
  float u[NN];              // power-iteration vector
  float scal[8];
  int icnt[4];
};

__device__ __forceinline__ float softplus_f(float x) {
  return fmaxf(x, 0.0f) + __logf(1.0f + __expf(-fabsf(x)));
}
__device__ __forceinline__ ull pk2(float lo, float hi) {
  ull r; asm("mov.b64 %0, {%1, %2};" : "=l"(r) : "f"(lo), "f"(hi)); return r;
}
__device__ __forceinline__ void upk2(ull v, float& lo, float& hi) {
  asm("mov.b64 {%0, %1}, %2;" : "=f"(lo), "=f"(hi) : "l"(v));
}
__device__ __forceinline__ ull fma2(ull a, ull b, ull c) {
  ull d; asm("fma.rn.f32x2 %0, %1, %2, %3;" : "=l"(d) : "l"(a), "l"(b), "l"(c));
  return d;
}
__device__ __forceinline__ ull add2(ull a, ull b) {
  ull d; asm("add.rn.f32x2 %0, %1, %2;" : "=l"(d) : "l"(a), "l"(b));
  return d;
}

__global__ void __launch_bounds__(NT, 1)
ts_gcn_kernel(const float* __restrict__ edge_pred,
              const int*   __restrict__ adj,
              const float* __restrict__ d_init,
              const float* __restrict__ u_init,
              const float* __restrict__ x_noise,
              float*       __restrict__ out)
{
  extern __shared__ __align__(16) char smem_raw[];
  Smem* sm = reinterpret_cast<Smem*>(smem_raw);
  const int b    = blockIdx.x;
  const int tid  = threadIdx.x;
  const int lane = tid & 31;
  const int wid  = tid >> 5;
  const int i_d  = tid & (NN - 1);
  const int g    = tid >> 7;        // j-group 0..3
  const int j0   = g * SEGJ;
  const float d0 = __ldg(d_init);

  const float4* epb4 = reinterpret_cast<const float4*>(edge_pred) + (size_t)b * NN * NN / 2;
  const int*    adjb = adj + (size_t)b * NN * NN;

  if (tid == 0) sm->icnt[0] = 0;

  // ---- A1: stage raw edge_pred (LDG.128 -> STS.128, coalesced) ---------------
  #pragma unroll
  for (int v = 0; v < 16; ++v) {
    int idx4 = v * NT + tid;               // 8192 float4 chunks
    int row = idx4 >> 6;                   // 64 float4 per row
    int col4 = idx4 & 63;
    *reinterpret_cast<float4*>(&sm->DW[row * PITCHD + col4 * 2]) = epb4[idx4];
  }
  // ---- A1b: adjacency bits via ballot ----------------------------------------
  #pragma unroll
  for (int v = 0; v < 32; ++v) {
    int word = v * 16 + wid;
    int i = word >> 2, q = word & 3;
    int a = adjb[i * NN + q * 32 + lane];
    unsigned m = __ballot_sync(0xffffffffu, a != 0);
    if (lane == 0) sm->bits[word] = m;
  }
  __syncthreads();

  // ---- A2: symmetrize + softplus over upper triangle --------------------------
  #pragma unroll
  for (int v = 0; v < 16; ++v) {
    int p = v * NT + tid;
    if (p < NPAIRS) {
      int r = p / 127, c = p - r * 127;
      int i, j;
      if (c >= r) { i = r; j = c + 1; }
      else        { i = 127 - r; j = 127 - c; }
      unsigned on = (sm->bits[(i << 2) + (j >> 5)] >> (j & 31)) & 1u;
      float2 e1 = sm->DW[i * PITCHD + j];
      float2 e2 = sm->DW[j * PITCHD + i];
      float2 dw = make_float2(0.0f, 0.0f);
      if (on) {
        dw.x = softplus_f(d0 + e1.x + e2.x);
        dw.y = softplus_f(d0 + e1.y + e2.y);
      }
      sm->DW[i * PITCHD + j] = dw;
      sm->DW[j * PITCHD + i] = dw;
    }
  }
  if (tid < NN) sm->DW[tid * PITCHD + tid] = make_float2(0.0f, 0.0f);
  __syncthreads();

  // ---- B: sum(adj) + row sums of D^2 -------------------------------------------
  {
    int cbit = __popc(sm->bits[tid]);
    #pragma unroll
    for (int o = 16; o; o >>= 1) cbit += __shfl_xor_sync(0xffffffffu, cbit, o);
    if (lane == 0) atomicAdd(&sm->icnt[0], cbit);
  }
  {
    float r0 = 0.0f, r1 = 0.0f;
    const float4* drow = reinterpret_cast<const float4*>(sm->DW + i_d * PITCHD + j0);
    #pragma unroll
    for (int t = 0; t < 16; ++t) {
      float4 q = drow[t];
      r0 = fmaf(q.x, q.x, r0);
      r1 = fmaf(q.z, q.z, r1);
    }
    float rp = r0 + r1;
    if (g) sm->part[(g - 1) * NN + i_d].x = rp;
    __syncthreads();
    if (g == 0) {
      rp += sm->part[i_d].x + sm->part[NN + i_d].x + sm->part[2 * NN + i_d].x;
      sm->rs[i_d] = rp;
    }
  }
  __syncthreads();
  if (tid < 32) {
    float m = sm->rs[tid] + sm->rs[tid + 32] + sm->rs[tid + 64] + sm->rs[tid + 96];
    #pragma unroll
    for (int o = 16; o; o >>= 1) m += __shfl_xor_sync(0xffffffffu, m, o);
    if (tid == 0) {
      float Nmol = 1.0f + (float)(__popc(sm->bits[0]) + __popc(sm->bits[1]) +
                                  __popc(sm->bits[2]) + __popc(sm->bits[3]));
      float invN = 1.0f / Nmol;
      sm->scal[0] = invN;
      sm->scal[1] = m * invN * invN;
      float S = 128.0f + (float)sm->icnt[0];
      sm->scal[2] = 0.4f / S;
    }
  }
  __syncthreads();

  // ---- B2: Gram matrix into registers ------------------------------------------
  float bg[SEGJ];
  {
    float invN = sm->scal[0], Moff = sm->scal[1];
    float rsi = sm->rs[i_d];
    unsigned wb = sm->bits[(i_d << 2) + (j0 >> 5)];
    const float4* drow = reinterpret_cast<const float4*>(sm->DW + i_d * PITCHD + j0);
    const float4* rsj  = reinterpret_cast<const float4*>(sm->rs + j0);
    #pragma unroll
    for (int t = 0; t < 8; ++t) {
      float4 rq = rsj[t];
      float4 q0 = drow[2 * t], q1 = drow[2 * t + 1];
      float dv[4] = {q0.x, q0.z, q1.x, q1.z};
      float rv[4] = {rq.x, rq.y, rq.z, rq.w};
      #pragma unroll
      for (int m = 0; m < 4; ++m) {
        int jj = 4 * t + m;
        int j = j0 + jj;
        bool on = (((wb >> jj) & 1u) != 0u) || (j == i_d);
        float val = -0.5f * (fmaf(dv[m], dv[m], Moff) - (rsi + rv[m]) * invN);
        bg[jj] = on ? val : 0.0f;
      }
    }
  }

  // ---- C: rank-3 power iteration, BG in regs, 4-way ILP --------------------------
  for (int k = 0; k < 3; ++k) {
    __syncthreads();
    if (tid < NN) sm->u[tid] = u_init[((size_t)b * NN + tid) * 3 + k];
    __syncthreads();
    for (int it = 0; it < 10; ++it) {
      float4 uv = reinterpret_cast<const float4*>(sm->u)[lane];
      float s = fmaf(uv.x, uv.x, fmaf(uv.y, uv.y, fmaf(uv.z, uv.z, uv.w * uv.w)));
      #pragma unroll
      for (int o = 16; o; o >>= 1) s += __shfl_xor_sync(0xffffffffu, s, o);
      float invn = rsqrtf(fmaxf(s, 1e-6f));   // == 1/max(sqrt(s), 0.001)
      float a0 = 0.0f, a1 = 0.0f, a2 = 0.0f, a3 = 0.0f;
      const float4* useg = reinterpret_cast<const float4*>(sm->u + j0);
      #pragma unroll
      for (int t = 0; t < 8; ++t) {
        float4 uq = useg[t];
        a0 = fmaf(bg[4 * t + 0], uq.x, a0);
        a1 = fmaf(bg[4 * t + 1], uq.y, a1);
        a2 = fmaf(bg[4 * t + 2], uq.z, a2);
        a3 = fmaf(bg[4 * t + 3], uq.w, a3);
      }
      float acc = (a0 + a1) + (a2 + a3);
      if (g) sm->part[(g - 1) * NN + i_d].x = acc;
      __syncthreads();
      if (g == 0) {
        acc += sm->part[i_d].x + sm->part[NN + i_d].x + sm->part[2 * NN + i_d].x;
        sm->u[i_d] = acc * invn;
      }
      __syncthreads();
    }
    float4 uv = reinterpret_cast<const float4*>(sm->u)[lane];
    float s = fmaf(uv.x, uv.x, fmaf(uv.y, uv.y, fmaf(uv.z, uv.z, uv.w * uv.w)));
    #pragma unroll
    for (int o = 16; o; o >>= 1) s += __shfl_xor_sync(0xffffffffu, s, o);
    float sc4 = rsqrtf(sqrtf(s + 0.01f));     // (eig_sq + 0.01)^-0.25
    __syncthreads();
    if (tid < NN) {
      float uk = sm->u[tid] * sc4;
      sm->u[tid] = uk;
      reinterpret_cast<float*>(&sm->Xs[tid])[k] =
          uk + x_noise[((size_t)b * NN + tid) * 3 + k];
    }
    __syncthreads();
    if (k < 2) {
      float ui = sm->u[i_d];
      const float4* useg = reinterpret_cast<const float4*>(sm->u + j0);
      #pragma unroll
      for (int t = 0; t < 8; ++t) {
        float4 uq = useg[t];
        bg[4 * t + 0] = fmaf(-ui, uq.x, bg[4 * t + 0]);
        bg[4 * t + 1] = fmaf(-ui, uq.y, bg[4 * t + 1]);
        bg[4 * t + 2] = fmaf(-ui, uq.z, bg[4 * t + 2]);
        bg[4 * t + 3] = fmaf(-ui, uq.w, bg[4 * t + 3]);
      }
    }
  }
  // finalize Xs.w = |x|^2
  if (tid < NN) {
    float4 x = sm->Xs[tid];
    x.w = fmaf(x.x, x.x, fmaf(x.y, x.y, x.z * x.z));
    sm->Xs[tid] = x;
  }

  // ---- preload packed (w*d) and (-w) for all 10 steps ----------------------------
  ull wd2[SEGJ / 2], wn2[SEGJ / 2];
  {
    const float4* drow = reinterpret_cast<const float4*>(sm->DW + i_d * PITCHD + j0);
    #pragma unroll
    for (int t = 0; t < 16; ++t) {
      float4 q = drow[t];                    // (d0,w0,d1,w1)
      wd2[t] = pk2(q.x * q.y, q.z * q.w);
      wn2[t] = pk2(-q.y, -q.w);
    }
  }
  const float cc = sm->scal[2];
  __syncthreads();

  // ---- D: 10 gradient-descent steps, packed f32x2, SoA-free ----------------------
  for (int ts = 0; ts < TSTEPS; ++ts) {
    float alpha = 0.1f + 4.9f * ((float)(TSTEPS - ts) * 0.1f);
    float4 xi = sm->Xs[i_d];
    ull m2x2 = pk2(-2.0f * xi.x, -2.0f * xi.x);
    ull m2y2 = pk2(-2.0f * xi.y, -2.0f * xi.y);
    ull m2z2 = pk2(-2.0f * xi.z, -2.0f * xi.z);
    float cbase = xi.w + 0.01f;
    ull cbase2 = pk2(cbase, cbase);
    ull cs2 = 0ull, ax2 = 0ull, ay2 = 0ull, az2 = 0ull;
    const float4* xrow = sm->Xs + j0;
    #pragma unroll
    for (int t = 0; t < SEGJ / 2; ++t) {
      float4 xa = xrow[2 * t];               // LDS.128 broadcast
      float4 xb = xrow[2 * t + 1];
      ull xjx = pk2(xa.x, xb.x);
      ull xjy = pk2(xa.y, xb.y);
      ull xjz = pk2(xa.z, xb.z);
      ull xjw = pk2(xa.w, xb.w);
      ull s2p = fma2(xjx, m2x2, xjw);
      s2p = fma2(xjy, m2y2, s2p);
      s2p = fma2(xjz, m2z2, s2p);
      s2p = add2(s2p, cbase2);
      float s0, s1;
      upk2(s2p, s0, s1);
      ull r2 = pk2(rsqrtf(s0), rsqrtf(s1));
      ull coef2 = fma2(wd2[t], r2, wn2[t]);  // w*(d/Dx - 1)
      cs2 = add2(cs2, coef2);
      ax2 = fma2(coef2, xjx, ax2);
      ay2 = fma2(coef2, xjy, ay2);
      az2 = fma2(coef2, xjz, az2);
    }
    float csl, csh, axl, axh, ayl, ayh, azl, azh;
    upk2(cs2, csl, csh); upk2(ax2, axl, axh);
    upk2(ay2, ayl, ayh); upk2(az2, azl, azh);
    float cs = csl + csh, ax = axl + axh, ay = ayl + ayh, az = azl + azh;
    if (g) sm->part[(g - 1) * NN + i_d] = make_float4(ax, ay, az, cs);
    __syncthreads();
    if (g == 0) {
      float4 p1 = sm->part[i_d], p2 = sm->part[NN + i_d], p3 = sm->part[2 * NN + i_d];
      float AX = ax + p1.x + p2.x + p3.x;
      float AY = ay + p1.y + p2.y + p3.y;
      float AZ = az + p1.z + p2.z + p3.z;
      float CS = cs + p1.w + p2.w + p3.w;
      float gx = fmaf(CS, xi.x, -AX) * cc;
      float gy = fmaf(CS, xi.y, -AY) * cc;
      float gz = fmaf(CS, xi.z, -AZ) * cc;
      float s2 = fmaf(gx, gx, fmaf(gy, gy, fmaf(gz, gz, 0.001f)));
      float inv_sp = rsqrtf(s2);
      float sp = s2 * inv_sp;
      float e = __expf(2.0f * (sp / alpha));
      float th = 1.0f - __fdividef(2.0f, e + 1.0f);
      float sc = alpha * th * inv_sp;
      xi.x = fmaf(gx, sc, xi.x);
      xi.y = fmaf(gy, sc, xi.y);
      xi.z = fmaf(gz, sc, xi.z);
      xi.w = fmaf(xi.x, xi.x, fmaf(xi.y, xi.y, xi.z * xi.z));
      sm->Xs[i_d] = xi;
    }
    __syncthreads();
  }

  // ---- E: output = adj * distances(X); sqrt via s*rsqrt(s) ------------------------
  float* outb = out + (size_t)b * NN * NN;
  #pragma unroll
  for (int v = 0; v < 8; ++v) {
    int f = v * NT + tid;
    int i = f >> 5;
    int jb = (f & 31) * 4;
    float4 xi = sm->Xs[i];
    unsigned wb = sm->bits[(i << 2) + (jb >> 5)];
    float4 r;
    #pragma unroll
    for (int m = 0; m < 4; ++m) {
      int j = jb + m;
      float4 xj = sm->Xs[j];
      float dx = xi.x - xj.x, dy = xi.y - xj.y, dz = xi.z - xj.z;
      float s = fmaf(dx, dx, fmaf(dy, dy, fmaf(dz, dz, 0.01f)));
      float val = ((wb >> (j & 31)) & 1u) ? s * rsqrtf(s) : 0.0f;
      reinterpret_cast<float*>(&r)[m] = val;
    }
    reinterpret_cast<float4*>(outb)[f] = r;
  }
}

extern "C" void kernel_launch(void* const* d_in, const int* in_sizes, int n_in,
                              void* d_out, int out_size) {
  const float* edge_pred = (const float*)d_in[0];
  const int*   adj       = (const int*)  d_in[1];
  const float* d_init    = (const float*)d_in[2];
  const float* u_init    = (const float*)d_in[3];
  const float* x_noise   = (const float*)d_in[4];
  float* out = (float*)d_out;

  size_t smem = sizeof(Smem);
  cudaFuncSetAttribute(ts_gcn_kernel,
                       cudaFuncAttributeMaxDynamicSharedMemorySize, (int)smem);
  ts_gcn_kernel<<<BATCH, NT, smem>>>(edge_pred, adj, d_init, u_init,
                                     x_noise, out);
}

// round 13
// speedup vs baseline: 1.7340x; 1.0387x over previous
#include <cuda_runtime.h>
#include <math.h>

#define NN 128
#define PITCHD 130   // float2 pitch: conflict-free LDS row reads
#define BATCH 512
#define NPAIRS 8128
#define NT 512
#define SEGJ 32
#define TSTEPS 10

typedef unsigned long long ull;

struct __align__(16) Smem {
  float2 DW[NN * PITCHD];   // (d,w) pairs, row-major, symmetric
  float4 Xs[NN];            // coordinates, .w = |x|^2
  float4 part[3 * NN];      // cross-group partials (phase B only)
  float  xsX[NN];           // SoA copies of X
  float  xsY[NN];
  float  xsZ[NN];
  float  xsW[NN];
  unsigned bits[NN * 4];    // adjacency bitmask
  float rs[NN];             // row sums of D^2
  float u0[NN];             // power-iteration ping
  float u1[NN];             // power-iteration pong
  float scal[8];
  int icnt[4];
};

__device__ __forceinline__ float softplus_f(float x) {
  return fmaxf(x, 0.0f) + __logf(1.0f + __expf(-fabsf(x)));
}
__device__ __forceinline__ ull pk2(float lo, float hi) {
  ull r; asm("mov.b64 %0, {%1, %2};" : "=l"(r) : "f"(lo), "f"(hi)); return r;
}
__device__ __forceinline__ void upk2(ull v, float& lo, float& hi) {
  asm("mov.b64 {%0, %1}, %2;" : "=f"(lo), "=f"(hi) : "l"(v));
}
__device__ __forceinline__ ull fma2(ull a, ull b, ull c) {
  ull d; asm("fma.rn.f32x2 %0, %1, %2, %3;" : "=l"(d) : "l"(a), "l"(b), "l"(c));
  return d;
}
__device__ __forceinline__ ull add2(ull a, ull b) {
  ull d; asm("add.rn.f32x2 %0, %1, %2;" : "=l"(d) : "l"(a), "l"(b));
  return d;
}

__global__ void __launch_bounds__(NT, 1)
ts_gcn_kernel(const float* __restrict__ edge_pred,
              const int*   __restrict__ adj,
              const float* __restrict__ d_init,
              const float* __restrict__ u_init,
              const float* __restrict__ x_noise,
              float*       __restrict__ out)
{
  extern __shared__ __align__(16) char smem_raw[];
  Smem* sm = reinterpret_cast<Smem*>(smem_raw);
  const int b    = blockIdx.x;
  const int tid  = threadIdx.x;
  const int lane = tid & 31;
  const int wid  = tid >> 5;
  const int i_d  = tid & (NN - 1);   // old mapping (phases A/B/E)
  const int g    = tid >> 7;
  const int j0   = g * SEGJ;
  // new warp-owns-rows mapping (phases B2/C/preload/D)
  const int row  = (wid << 3) + (lane & 7);   // 16 warps x 8 rows = 128
  const int seg  = lane >> 3;                 // 0..3
  const int j0n  = seg * SEGJ;
  const float d0 = __ldg(d_init);

  const float2* epb  = reinterpret_cast<const float2*>(edge_pred) + (size_t)b * NN * NN;
  const int*    adjb = adj + (size_t)b * NN * NN;

  if (tid == 0) sm->icnt[0] = 0;

  // ---- A1: stage raw edge_pred (coalesced) -----------------------------------
  #pragma unroll
  for (int v = 0; v < 32; ++v) {
    int idx = v * NT + tid;
    sm->DW[(idx >> 7) * PITCHD + (idx & (NN - 1))] = epb[idx];
  }
  // ---- A1b: adjacency bits via ballot -----------------------------------------
  #pragma unroll
  for (int v = 0; v < 32; ++v) {
    int word = v * 16 + wid;
    int i = word >> 2, q = word & 3;
    int a = adjb[i * NN + q * 32 + lane];
    unsigned m = __ballot_sync(0xffffffffu, a != 0);
    if (lane == 0) sm->bits[word] = m;
  }
  __syncthreads();

  // ---- A2: symmetrize + softplus over upper triangle --------------------------
  #pragma unroll
  for (int v = 0; v < 16; ++v) {
    int p = v * NT + tid;
    if (p < NPAIRS) {
      int r = p / 127, c = p - r * 127;
      int i, j;
      if (c >= r) { i = r; j = c + 1; }
      else        { i = 127 - r; j = 127 - c; }
      unsigned on = (sm->bits[(i << 2) + (j >> 5)] >> (j & 31)) & 1u;
      float2 e1 = sm->DW[i * PITCHD + j];
      float2 e2 = sm->DW[j * PITCHD + i];
      float2 dw = make_float2(0.0f, 0.0f);
      if (on) {
        dw.x = softplus_f(d0 + e1.x + e2.x);
        dw.y = softplus_f(d0 + e1.y + e2.y);
      }
      sm->DW[i * PITCHD + j] = dw;
      sm->DW[j * PITCHD + i] = dw;
    }
  }
  if (tid < NN) sm->DW[tid * PITCHD + tid] = make_float2(0.0f, 0.0f);
  __syncthreads();

  // ---- B: sum(adj) + row sums of D^2 (old mapping) -----------------------------
  {
    int cbit = __popc(sm->bits[tid]);
    #pragma unroll
    for (int o = 16; o; o >>= 1) cbit += __shfl_xor_sync(0xffffffffu, cbit, o);
    if (lane == 0) atomicAdd(&sm->icnt[0], cbit);
  }
  {
    float rp = 0.0f;
    const float4* drow = reinterpret_cast<const float4*>(sm->DW + i_d * PITCHD + j0);
    #pragma unroll
    for (int t = 0; t < 16; ++t) {
      float4 q = drow[t];
      rp = fmaf(q.x, q.x, rp);
      rp = fmaf(q.z, q.z, rp);
    }
    if (g) sm->part[(g - 1) * NN + i_d].x = rp;
    __syncthreads();
    if (g == 0) {
      rp += sm->part[i_d].x + sm->part[NN + i_d].x + sm->part[2 * NN + i_d].x;
      sm->rs[i_d] = rp;
    }
  }
  __syncthreads();
  if (tid < 32) {
    float m = sm->rs[tid] + sm->rs[tid + 32] + sm->rs[tid + 64] + sm->rs[tid + 96];
    #pragma unroll
    for (int o = 16; o; o >>= 1) m += __shfl_xor_sync(0xffffffffu, m, o);
    if (tid == 0) {
      float Nmol = 1.0f + (float)(__popc(sm->bits[0]) + __popc(sm->bits[1]) +
                                  __popc(sm->bits[2]) + __popc(sm->bits[3]));
      float invN = 1.0f / Nmol;
      sm->scal[0] = invN;
      sm->scal[1] = m * invN * invN;
      float S = 128.0f + (float)sm->icnt[0];
      sm->scal[2] = 0.4f / S;
    }
  }
  __syncthreads();

  // ---- B2: Gram matrix into registers (new mapping: row, j0n) ------------------
  float bg[SEGJ];
  {
    float invN = sm->scal[0], Moff = sm->scal[1];
    float rsi = sm->rs[row];
    unsigned wb = sm->bits[(row << 2) + seg];
    const float4* drow = reinterpret_cast<const float4*>(sm->DW + row * PITCHD + j0n);
    const float4* rsj  = reinterpret_cast<const float4*>(sm->rs + j0n);
    #pragma unroll
    for (int t = 0; t < 8; ++t) {
      float4 rq = rsj[t];
      float4 q0 = drow[2 * t], q1 = drow[2 * t + 1];
      float dv[4] = {q0.x, q0.z, q1.x, q1.z};
      float rv[4] = {rq.x, rq.y, rq.z, rq.w};
      #pragma unroll
      for (int m = 0; m < 4; ++m) {
        int jj = 4 * t + m;
        int j = j0n + jj;
        bool on = (((wb >> jj) & 1u) != 0u) || (j == row);
        float val = -0.5f * (fmaf(dv[m], dv[m], Moff) - (rsi + rv[m]) * invN);
        bg[jj] = on ? val : 0.0f;
      }
    }
  }

  // ---- C: rank-3 power iteration, normalization-free, 1 barrier/iter ----------
  for (int k = 0; k < 3; ++k) {
    __syncthreads();   // prior uses of u0/u1 complete
    if (tid < NN) sm->u0[tid] = u_init[((size_t)b * NN + tid) * 3 + k];
    __syncthreads();
    #pragma unroll
    for (int it = 0; it < 10; ++it) {
      const float* uc = (it & 1) ? sm->u1 : sm->u0;
      float*       un = (it & 1) ? sm->u0 : sm->u1;
      float a0 = 0.f, a1 = 0.f, a2 = 0.f, a3 = 0.f;
      const float4* useg = reinterpret_cast<const float4*>(uc + j0n);
      #pragma unroll
      for (int t = 0; t < 8; ++t) {
        float4 uq = useg[t];
        a0 = fmaf(bg[4 * t + 0], uq.x, a0);
        a1 = fmaf(bg[4 * t + 1], uq.y, a1);
        a2 = fmaf(bg[4 * t + 2], uq.z, a2);
        a3 = fmaf(bg[4 * t + 3], uq.w, a3);
      }
      float acc = (a0 + a1) + (a2 + a3);
      acc += __shfl_xor_sync(0xffffffffu, acc, 8);
      acc += __shfl_xor_sync(0xffffffffu, acc, 16);
      if (lane < 8) un[row] = acc * 0.00390625f;   // 2^-8 rescale
      __syncthreads();
    }
    // after 10 iters: w10 in u0, w9 in u1
    float4 v0 = reinterpret_cast<const float4*>(sm->u0)[lane];
    float4 v1 = reinterpret_cast<const float4*>(sm->u1)[lane];
    float n10 = fmaf(v0.x, v0.x, fmaf(v0.y, v0.y, fmaf(v0.z, v0.z, v0.w * v0.w)));
    float n9  = fmaf(v1.x, v1.x, fmaf(v1.y, v1.y, fmaf(v1.z, v1.z, v1.w * v1.w)));
    #pragma unroll
    for (int o = 16; o; o >>= 1) {
      n10 += __shfl_xor_sync(0xffffffffu, n10, o);
      n9  += __shfl_xor_sync(0xffffffffu, n9, o);
    }
    // eig_sq = 2^16 * n10 / n9 ; u_final = 2^8 * rsqrt(n9) * (eig+0.01)^-0.25 * w10
    float eig = 65536.0f * n10 / n9;
    float f = 256.0f * rsqrtf(n9) * rsqrtf(sqrtf(eig + 0.01f));
    __syncthreads();   // all reads of u1 done before overwrite
    if (lane < 8) {
      float uf = sm->u0[row] * f;
      sm->u1[row] = uf;                              // u_final
      reinterpret_cast<float*>(&sm->Xs[row])[k] =
          uf + x_noise[((size_t)b * NN + row) * 3 + k];
    }
    __syncthreads();
    if (k < 2) {   // deflate: bg -= uf uf^T
      float ui = sm->u1[row];
      const float4* us = reinterpret_cast<const float4*>(sm->u1 + j0n);
      #pragma unroll
      for (int t = 0; t < 8; ++t) {
        float4 uq = us[t];
        bg[4 * t + 0] = fmaf(-ui, uq.x, bg[4 * t + 0]);
        bg[4 * t + 1] = fmaf(-ui, uq.y, bg[4 * t + 1]);
        bg[4 * t + 2] = fmaf(-ui, uq.z, bg[4 * t + 2]);
        bg[4 * t + 3] = fmaf(-ui, uq.w, bg[4 * t + 3]);
      }
    }
  }
  __syncthreads();
  // finalize Xs.w = |x|^2 and SoA copies
  if (tid < NN) {
    float4 x = sm->Xs[tid];
    x.w = fmaf(x.x, x.x, fmaf(x.y, x.y, x.z * x.z));
    sm->Xs[tid] = x;
    sm->xsX[tid] = x.x; sm->xsY[tid] = x.y;
    sm->xsZ[tid] = x.z; sm->xsW[tid] = x.w;
  }

  // ---- preload packed (w*d) and (-w) (new mapping) -----------------------------
  ull wd2[SEGJ / 2], wn2[SEGJ / 2];
  {
    const float4* drow = reinterpret_cast<const float4*>(sm->DW + row * PITCHD + j0n);
    #pragma unroll
    for (int t = 0; t < 16; ++t) {
      float4 q = drow[t];                    // (d0,w0,d1,w1)
      wd2[t] = pk2(q.x * q.y, q.z * q.w);
      wn2[t] = pk2(-q.y, -q.w);
    }
  }
  const float cc = sm->scal[2];
  __syncthreads();

  // ---- D: 10 gradient-descent steps, packed f32x2, 1 barrier/step --------------
  for (int ts = 0; ts < TSTEPS; ++ts) {
    float alpha = 0.1f + 4.9f * ((float)(TSTEPS - ts) * 0.1f);
    float xix = sm->xsX[row], xiy = sm->xsY[row];
    float xiz = sm->xsZ[row], xiw = sm->xsW[row];
    ull m2x2 = pk2(-2.0f * xix, -2.0f * xix);
    ull m2y2 = pk2(-2.0f * xiy, -2.0f * xiy);
    ull m2z2 = pk2(-2.0f * xiz, -2.0f * xiz);
    float cbase = xiw + 0.01f;
    ull cbase2 = pk2(cbase, cbase);
    ull cs2 = 0ull, ax2 = 0ull, ay2 = 0ull, az2 = 0ull;
    const ull* pX = reinterpret_cast<const ull*>(sm->xsX + j0n);
    const ull* pY = reinterpret_cast<const ull*>(sm->xsY + j0n);
    const ull* pZ = reinterpret_cast<const ull*>(sm->xsZ + j0n);
    const ull* pW = reinterpret_cast<const ull*>(sm->xsW + j0n);
    #pragma unroll
    for (int t = 0; t < SEGJ / 2; ++t) {
      ull xjx = pX[t], xjy = pY[t], xjz = pZ[t], xjw = pW[t];
      ull s2p = fma2(xjx, m2x2, xjw);
      s2p = fma2(xjy, m2y2, s2p);
      s2p = fma2(xjz, m2z2, s2p);
      s2p = add2(s2p, cbase2);               // |xi-xj|^2 + 0.01 (two j's)
      float s0, s1;
      upk2(s2p, s0, s1);
      ull r2 = pk2(rsqrtf(s0), rsqrtf(s1));
      ull coef2 = fma2(wd2[t], r2, wn2[t]);  // w*(d/Dx - 1)
      cs2 = add2(cs2, coef2);
      ax2 = fma2(coef2, xjx, ax2);
      ay2 = fma2(coef2, xjy, ay2);
      az2 = fma2(coef2, xjz, az2);
    }
    float csl, csh, axl, axh, ayl, ayh, azl, azh;
    upk2(cs2, csl, csh); upk2(ax2, axl, axh);
    upk2(ay2, ayl, ayh); upk2(az2, azl, azh);
    float cs = csl + csh, ax = axl + axh, ay = ayl + ayh, az = azl + azh;
    cs += __shfl_xor_sync(0xffffffffu, cs, 8);
    ax += __shfl_xor_sync(0xffffffffu, ax, 8);
    ay += __shfl_xor_sync(0xffffffffu, ay, 8);
    az += __shfl_xor_sync(0xffffffffu, az, 8);
    cs += __shfl_xor_sync(0xffffffffu, cs, 16);
    ax += __shfl_xor_sync(0xffffffffu, ax, 16);
    ay += __shfl_xor_sync(0xffffffffu, ay, 16);
    az += __shfl_xor_sync(0xffffffffu, az, 16);
    if (lane < 8) {
      float gx = fmaf(cs, xix, -ax) * cc;
      float gy = fmaf(cs, xiy, -ay) * cc;
      float gz = fmaf(cs, xiz, -az) * cc;
      float s2 = fmaf(gx, gx, fmaf(gy, gy, fmaf(gz, gz, 0.001f)));
      float inv_sp = rsqrtf(s2);
      float sp = s2 * inv_sp;
      float e = __expf(2.0f * (sp / alpha));
      float th = 1.0f - __fdividef(2.0f, e + 1.0f);   // tanh(sp/alpha)
      float sc = alpha * th * inv_sp;
      float nx = fmaf(gx, sc, xix);
      float ny = fmaf(gy, sc, xiy);
      float nz = fmaf(gz, sc, xiz);
      float nw = fmaf(nx, nx, fmaf(ny, ny, nz * nz));
      sm->xsX[row] = nx; sm->xsY[row] = ny;
      sm->xsZ[row] = nz; sm->xsW[row] = nw;
      sm->Xs[row] = make_float4(nx, ny, nz, nw);
    }
    __syncthreads();
  }

  // ---- E: output = adj * distances(X) -------------------------------------------
  float* outb = out + (size_t)b * NN * NN;
  #pragma unroll
  for (int v = 0; v < 8; ++v) {
    int f = v * NT + tid;
    int i = f >> 5;
    int jb = (f & 31) * 4;
    float4 xi = sm->Xs[i];
    unsigned wb = sm->bits[(i << 2) + (jb >> 5)];
    float4 r;
    #pragma unroll
    for (int m = 0; m < 4; ++m) {
      int j = jb + m;
      float4 xj = sm->Xs[j];
      float dx = xi.x - xj.x, dy = xi.y - xj.y, dz = xi.z - xj.z;
      float s = fmaf(dx, dx, fmaf(dy, dy, fmaf(dz, dz, 0.01f)));
      float val = ((wb >> (j & 31)) & 1u) ? sqrtf(s) : 0.0f;
      reinterpret_cast<float*>(&r)[m] = val;
    }
    reinterpret_cast<float4*>(outb)[f] = r;
  }
}

extern "C" void kernel_launch(void* const* d_in, const int* in_sizes, int n_in,
                              void* d_out, int out_size) {
  const float* edge_pred = (const float*)d_in[0];
  const int*   adj       = (const int*)  d_in[1];
  const float* d_init    = (const float*)d_in[2];
  const float* u_init    = (const float*)d_in[3];
  const float* x_noise   = (const float*)d_in[4];
  float* out = (float*)d_out;

  size_t smem = sizeof(Smem);
  cudaFuncSetAttribute(ts_gcn_kernel,
                       cudaFuncAttributeMaxDynamicSharedMemorySize, (int)smem);
  ts_gcn_kernel<<<BATCH, NT, smem>>>(edge_pred, adj, d_init, u_init,
                                     x_noise, out);
}